// round 3
// baseline (speedup 1.0000x reference)
#include <cuda_runtime.h>
#include <cuda_bf16.h>
#include <math.h>

// ---------------------------------------------------------------------------
// Problem constants (fixed shapes from reference setup_inputs)
// ---------------------------------------------------------------------------
#define NN 100000
#define EE 3200000
#define F0 512
#define F1 256
#define F2 256
#define F3 64

// ---------------------------------------------------------------------------
// Scratch: __device__ globals (no allocations allowed)
// ---------------------------------------------------------------------------
__device__ float g_A[(size_t)NN * 256];   // ping
__device__ float g_B[(size_t)NN * 256];   // pong
__device__ float g_C[(size_t)NN * 64];    // pre-softmax support
__device__ int   g_rowptr[NN + 1];
__device__ int   g_cursor[NN];            // doubles as histogram counts
__device__ int   g_cols[EE];
__device__ float g_vals[EE];
__device__ int   g_bsums[128];

// ---------------------------------------------------------------------------
// CSR build: histogram -> exclusive scan -> scatter
// ---------------------------------------------------------------------------
__global__ void k_zero_int(int* p, int n) {
    int i = blockIdx.x * blockDim.x + threadIdx.x;
    if (i < n) p[i] = 0;
}

__global__ void k_hist(const int* __restrict__ erow) {
    int e = blockIdx.x * blockDim.x + threadIdx.x;
    if (e < EE) atomicAdd(&g_cursor[erow[e]], 1);
}

// Per-block exclusive scan over counts (n = NN+1 logical elems, counts[i>=NN]=0)
__global__ void k_scan_block(int n) {
    int tid  = threadIdx.x;
    int i    = blockIdx.x * 1024 + tid;
    int v    = (i < NN) ? g_cursor[i] : 0;
    int lane = tid & 31, warp = tid >> 5;
    int x = v;
    #pragma unroll
    for (int o = 1; o < 32; o <<= 1) {
        int y = __shfl_up_sync(0xFFFFFFFFu, x, o);
        if (lane >= o) x += y;
    }
    __shared__ int wsum[32];
    if (lane == 31) wsum[warp] = x;
    __syncthreads();
    if (warp == 0) {
        int w = wsum[lane];
        #pragma unroll
        for (int o = 1; o < 32; o <<= 1) {
            int y = __shfl_up_sync(0xFFFFFFFFu, w, o);
            if (lane >= o) w += y;
        }
        wsum[lane] = w;
    }
    __syncthreads();
    int incl = x + (warp > 0 ? wsum[warp - 1] : 0);
    if (i < n) g_rowptr[i] = incl - v;  // exclusive within block
    if (tid == 1023) g_bsums[blockIdx.x] = incl;
}

__global__ void k_scan_spine(int nb) {   // single block, 128 threads
    int tid = threadIdx.x;
    int lane = tid & 31, warp = tid >> 5;
    int v = (tid < nb) ? g_bsums[tid] : 0;
    int x = v;
    #pragma unroll
    for (int o = 1; o < 32; o <<= 1) {
        int y = __shfl_up_sync(0xFFFFFFFFu, x, o);
        if (lane >= o) x += y;
    }
    __shared__ int ws[4];
    if (lane == 31) ws[warp] = x;
    __syncthreads();
    int off = 0;
    for (int w = 0; w < warp; w++) off += ws[w];
    if (tid < nb) g_bsums[tid] = (x + off) - v;  // exclusive
}

__global__ void k_scan_add(int n) {
    int i = blockIdx.x * 1024 + threadIdx.x;
    if (i < n) g_rowptr[i] += g_bsums[blockIdx.x];
}

__global__ void k_scatter(const int* __restrict__ erow,
                          const int* __restrict__ ecol,
                          const float* __restrict__ eval) {
    int e = blockIdx.x * blockDim.x + threadIdx.x;
    if (e < EE) {
        int r = erow[e];
        int p = g_rowptr[r] + atomicAdd(&g_cursor[r], 1);
        g_cols[p] = ecol[e];
        g_vals[p] = eval[e];
    }
}

// ---------------------------------------------------------------------------
// Dense GEMM: C[M,N] = A[M,K] @ W[K,N]   (fp32, 128x64 tile, 8x4 microtile)
// ---------------------------------------------------------------------------
#define GBM 128
#define GBN 64
#define GBK 16

__global__ __launch_bounds__(256) void k_gemm(
    const float* __restrict__ A, const float* __restrict__ W,
    float* __restrict__ C, int M, int N, int K)
{
    __shared__ float As[GBK][GBM];
    __shared__ float Ws[GBK][GBN];

    int tid = threadIdx.x;
    int m0 = blockIdx.y * GBM, n0 = blockIdx.x * GBN;
    int tx = tid & 15, ty = tid >> 4;
    int tm = ty * 8, tn = tx * 4;

    // A-load mapping: 128 rows x 16 cols per tile, float4 per thread x2
    int alm = tid >> 2;        // 0..63
    int alk = (tid & 3) * 4;   // 0,4,8,12
    // W-load mapping: 16 rows x 64 cols, scalar x4
    int wk = tid >> 6;         // 0..3
    int wn = tid & 63;

    float acc[8][4];
    #pragma unroll
    for (int i = 0; i < 8; i++)
        #pragma unroll
        for (int j = 0; j < 4; j++) acc[i][j] = 0.f;

    for (int k0 = 0; k0 < K; k0 += GBK) {
        #pragma unroll
        for (int h = 0; h < 2; h++) {
            int m = m0 + alm + h * 64;
            float4 av = make_float4(0.f, 0.f, 0.f, 0.f);
            if (m < M) av = *(const float4*)&A[(size_t)m * K + k0 + alk];
            As[alk + 0][alm + h * 64] = av.x;
            As[alk + 1][alm + h * 64] = av.y;
            As[alk + 2][alm + h * 64] = av.z;
            As[alk + 3][alm + h * 64] = av.w;
        }
        #pragma unroll
        for (int h = 0; h < 4; h++) {
            int k = wk + h * 4;
            Ws[k][wn] = W[(size_t)(k0 + k) * N + n0 + wn];
        }
        __syncthreads();

        #pragma unroll
        for (int k = 0; k < GBK; k++) {
            float ar[8], br[4];
            *(float4*)&ar[0] = *(const float4*)&As[k][tm];
            *(float4*)&ar[4] = *(const float4*)&As[k][tm + 4];
            *(float4*)&br[0] = *(const float4*)&Ws[k][tn];
            #pragma unroll
            for (int i = 0; i < 8; i++)
                #pragma unroll
                for (int j = 0; j < 4; j++)
                    acc[i][j] = fmaf(ar[i], br[j], acc[i][j]);
        }
        __syncthreads();
    }

    #pragma unroll
    for (int i = 0; i < 8; i++) {
        int row = m0 + tm + i;
        if (row < M) {
            float4 v = make_float4(acc[i][0], acc[i][1], acc[i][2], acc[i][3]);
            *(float4*)&C[(size_t)row * N + n0 + tn] = v;
        }
    }
}

// ---------------------------------------------------------------------------
// SpMM F=256: out[row] = sum_e val_e * sup[col_e]  (+bias, relu)
// One block per row, thread = feature column. Atomic-free.
// ---------------------------------------------------------------------------
__global__ __launch_bounds__(256) void k_spmm256(
    const float* __restrict__ sup, const float* __restrict__ bias,
    float* __restrict__ out)
{
    int row = blockIdx.x;
    int tid = threadIdx.x;
    int s = g_rowptr[row], e = g_rowptr[row + 1];

    float acc0 = 0.f, acc1 = 0.f;
    int i = s;
    for (; i + 4 <= e; i += 4) {
        int   c0 = g_cols[i],     c1 = g_cols[i + 1];
        int   c2 = g_cols[i + 2], c3 = g_cols[i + 3];
        float v0 = g_vals[i],     v1 = g_vals[i + 1];
        float v2 = g_vals[i + 2], v3 = g_vals[i + 3];
        acc0 = fmaf(v0, sup[(size_t)c0 * 256 + tid], acc0);
        acc1 = fmaf(v1, sup[(size_t)c1 * 256 + tid], acc1);
        acc0 = fmaf(v2, sup[(size_t)c2 * 256 + tid], acc0);
        acc1 = fmaf(v3, sup[(size_t)c3 * 256 + tid], acc1);
    }
    for (; i < e; i++) {
        acc0 = fmaf(g_vals[i], sup[(size_t)g_cols[i] * 256 + tid], acc0);
    }
    float acc = acc0 + acc1 + bias[tid];
    acc = fmaxf(acc, 0.f);   // relu (both F=256 layers are relu'd)
    out[(size_t)row * 256 + tid] = acc;
}

// ---------------------------------------------------------------------------
// SpMM F=64 + bias + log_softmax, one block (64 threads) per row
// ---------------------------------------------------------------------------
__global__ __launch_bounds__(64) void k_spmm64_lsm(
    const float* __restrict__ sup, const float* __restrict__ b3,
    float* __restrict__ out)
{
    int row = blockIdx.x;
    int tid = threadIdx.x;
    int s = g_rowptr[row], e = g_rowptr[row + 1];

    float acc0 = 0.f, acc1 = 0.f;
    int i = s;
    for (; i + 4 <= e; i += 4) {
        int   c0 = g_cols[i],     c1 = g_cols[i + 1];
        int   c2 = g_cols[i + 2], c3 = g_cols[i + 3];
        float v0 = g_vals[i],     v1 = g_vals[i + 1];
        float v2 = g_vals[i + 2], v3 = g_vals[i + 3];
        acc0 = fmaf(v0, sup[(size_t)c0 * 64 + tid], acc0);
        acc1 = fmaf(v1, sup[(size_t)c1 * 64 + tid], acc1);
        acc0 = fmaf(v2, sup[(size_t)c2 * 64 + tid], acc0);
        acc1 = fmaf(v3, sup[(size_t)c3 * 64 + tid], acc1);
    }
    for (; i < e; i++) {
        acc0 = fmaf(g_vals[i], sup[(size_t)g_cols[i] * 64 + tid], acc0);
    }
    float acc = acc0 + acc1 + b3[tid];

    int lane = tid & 31, warp = tid >> 5;
    __shared__ float wred[2];

    // row max
    float m = acc;
    #pragma unroll
    for (int o = 16; o > 0; o >>= 1)
        m = fmaxf(m, __shfl_xor_sync(0xFFFFFFFFu, m, o));
    if (lane == 0) wred[warp] = m;
    __syncthreads();
    float M = fmaxf(wred[0], wred[1]);
    __syncthreads();

    // sum of exp
    float ex = expf(acc - M);
    float sum = ex;
    #pragma unroll
    for (int o = 16; o > 0; o >>= 1)
        sum += __shfl_xor_sync(0xFFFFFFFFu, sum, o);
    if (lane == 0) wred[warp] = sum;
    __syncthreads();
    float S = wred[0] + wred[1];

    out[(size_t)row * 64 + tid] = acc - M - logf(S);
}

// ---------------------------------------------------------------------------
// Launch
// ---------------------------------------------------------------------------
extern "C" void kernel_launch(void* const* d_in, const int* in_sizes, int n_in,
                              void* d_out, int out_size)
{
    const float* x    = (const float*)d_in[0];
    const int*   erow = (const int*)  d_in[1];
    const int*   ecol = (const int*)  d_in[2];
    const float* eval = (const float*)d_in[3];
    const float* W1   = (const float*)d_in[4];
    const float* b1   = (const float*)d_in[5];
    const float* W2   = (const float*)d_in[6];
    const float* b2   = (const float*)d_in[7];
    const float* W3   = (const float*)d_in[8];
    const float* b3   = (const float*)d_in[9];
    float* out = (float*)d_out;

    // resolve device-global addresses (host-side query, capture-safe)
    float *dA, *dB, *dC;
    int *dCur;
    cudaGetSymbolAddress((void**)&dA,   g_A);
    cudaGetSymbolAddress((void**)&dB,   g_B);
    cudaGetSymbolAddress((void**)&dC,   g_C);
    cudaGetSymbolAddress((void**)&dCur, g_cursor);

    const int NB_SCAN = (NN + 1 + 1023) / 1024;   // 98
    const int EB = (EE + 255) / 256;

    // --- CSR build ---
    k_zero_int<<<(NN + 255) / 256, 256>>>(dCur, NN);
    k_hist<<<EB, 256>>>(erow);
    k_scan_block<<<NB_SCAN, 1024>>>(NN + 1);
    k_scan_spine<<<1, 128>>>(NB_SCAN);
    k_scan_add<<<NB_SCAN, 1024>>>(NN + 1);
    k_zero_int<<<(NN + 255) / 256, 256>>>(dCur, NN);
    k_scatter<<<EB, 256>>>(erow, ecol, eval);

    // --- layer 1: s1 = x @ W1 ; h1 = relu(spmm(s1) + b1) ---
    {
        dim3 grid(F1 / GBN, (NN + GBM - 1) / GBM);
        k_gemm<<<grid, 256>>>(x, W1, dA, NN, F1, F0);
    }
    k_spmm256<<<NN, 256>>>(dA, b1, dB);

    // --- layer 2: s2 = h1 @ W2 ; h2 = relu(spmm(s2) + b2) ---
    {
        dim3 grid(F2 / GBN, (NN + GBM - 1) / GBM);
        k_gemm<<<grid, 256>>>(dB, W2, dA, NN, F2, F1);
    }
    k_spmm256<<<NN, 256>>>(dA, b2, dB);

    // --- layer 3: s3 = h2 @ W3 ; out = log_softmax(spmm(s3) + b3) ---
    {
        dim3 grid(F3 / GBN, (NN + GBM - 1) / GBM);
        k_gemm<<<grid, 256>>>(dB, W3, dC, NN, F3, F2);
    }
    k_spmm64_lsm<<<NN, 64>>>(dC, b3, out);
}